// round 15
// baseline (speedup 1.0000x reference)
#include <cuda_runtime.h>
#include <cstdint>

// VQ nearest-codebook via mma.sync m16n8k8 tf32, 3-term Dekker split
// (S = Xhi*Chi + Xlo*Chi + Xhi*Clo), fused argmin.
// A fragments (warp's 16 points, hi+lo) live in REGISTERS for the whole
// kernel; the phase loop reads only B from smem. 256 thr, 8 warps, 2 CTA/SM.

#define DD 64
#define KTOT 1024
#define PTS 128
#define NTHREADS 256
#define NCHUNK 16            // chunks of 64 codewords
#define CHUNK_F 5120         // floats per permuted B chunk
#define NT_STRIDE 640        // 32 lanes * 20
#define L_STRIDE 20          // padded lane stride (conflict-free)

// smem float offsets
#define A_HI_OFF 0           // 8 tiles * 1024 (staging only)
#define A_LO_OFF 8192
#define B0_OFF   16384
#define B1_OFF   21504
#define SMEM_FLOATS 26624    // 104 KB

__device__ float g_Bhi[NCHUNK * CHUNK_F];
__device__ float g_Blo[NCHUNK * CHUNK_F];
__device__ float g_cnorm[KTOT];

#define CP_ASYNC16(dst, src) \
    asm volatile("cp.async.ca.shared.global [%0], [%1], 16;" :: "r"(dst), "l"(src))
#define CP_COMMIT() asm volatile("cp.async.commit_group;" ::: "memory")
#define CP_WAIT0()  asm volatile("cp.async.wait_group 0;" ::: "memory")

#define MMA_TF32(d, a, b0, b1)                                                 \
    asm volatile("mma.sync.aligned.m16n8k8.row.col.f32.tf32.tf32.f32 "         \
        "{%0,%1,%2,%3}, {%4,%5,%6,%7}, {%8,%9}, {%0,%1,%2,%3};"                \
        : "+f"((d)[0]), "+f"((d)[1]), "+f"((d)[2]), "+f"((d)[3])               \
        : "r"((a).x), "r"((a).y), "r"((a).z), "r"((a).w), "r"(b0), "r"(b1))

__device__ __forceinline__ float tf32r(float v) {
    uint32_t r;
    asm("cvt.rna.tf32.f32 %0, %1;" : "=r"(r) : "f"(v));
    return __uint_as_float(r);
}
__device__ __forceinline__ uint32_t ord_f32(float f) {
    uint32_t u = __float_as_uint(f);
    return (u & 0x80000000u) ? ~u : (u | 0x80000000u);
}

// ---- prep: tf32 hi/lo codebook permuted into B-fragment order --------------
__global__ void __launch_bounds__(256)
prep_cb(const float* __restrict__ cb) {
    int k = blockIdx.x * blockDim.x + threadIdx.x;
    if (k >= KTOT) return;
    const int chunk = k >> 6, ck = k & 63, nt = ck >> 3, g = ck & 7;
    float s = 0.f;
#pragma unroll
    for (int d = 0; d < DD; d++) {
        float v = cb[(size_t)k * DD + d];
        s += v * v;
        float hi = tf32r(v);
        float lo = tf32r(v - hi);
        int kk = d >> 3, c = d & 7, tig = c & 3, reg = c >> 2;
        int addr = chunk * CHUNK_F + nt * NT_STRIDE + (g * 4 + tig) * L_STRIDE
                 + kk * 2 + reg;
        g_Bhi[addr] = hi;
        g_Blo[addr] = lo;
    }
    g_cnorm[k] = s;
}

// ---- main: GEMM + fused argmin + gather -----------------------------------
__global__ void __launch_bounds__(NTHREADS, 2)
vq_main(const float* __restrict__ x, const float* __restrict__ cb,
        float* __restrict__ out, int write_idx) {
    extern __shared__ float smem[];
    const int tid  = threadIdx.x;
    const int w    = tid >> 5;      // warp -> tile w (points w*16 .. w*16+15)
    const int lane = tid & 31;
    const int g    = lane >> 2;
    const int tig  = lane & 3;

    const int bh0 = blockIdx.x * 2;
    const int b   = bh0 >> 6;
    const int h0  = bh0 & 63;
    const float* xbase = x + (size_t)b * (DD * 4096) + (size_t)h0 * 64;

    uint32_t sbase;
    asm("{ .reg .u64 t; cvta.to.shared.u64 t, %1; cvt.u32.u64 %0, t; }"
        : "=r"(sbase) : "l"(smem));

    // Prefetch phase 0 (chunk 0 hi). 20 floats/thread linear.
#pragma unroll
    for (int q = 0; q < 5; q++)
        CP_ASYNC16(sbase + (uint32_t)(B0_OFF + tid * L_STRIDE + q * 4) * 4u,
                   g_Bhi + tid * L_STRIDE + q * 4);
    CP_COMMIT();

    // Stage A: x -> tf32 hi/lo in fragment order (smem staging).
    for (int i = tid; i < DD * 32; i += NTHREADS) {
        int d  = i >> 5;
        int p4 = (i & 31) * 4;
        float4 v = *(const float4*)(xbase + (size_t)d * 4096 + (p4 >> 6) * 64 + (p4 & 63));
        float e[4] = {v.x, v.y, v.z, v.w};
        int kk = d >> 3, c = d & 7, tg = c & 3, chalf = (c >> 2) * 2;
#pragma unroll
        for (int q = 0; q < 4; q++) {
            int p = p4 + q, tt = p >> 4, r = p & 15, gg = r & 7, half = r >> 3;
            int idx = tt * 1024 + kk * 128 + (gg * 4 + tg) * 4 + chalf + half;
            float hi = tf32r(e[q]);
            smem[A_HI_OFF + idx] = hi;
            smem[A_LO_OFF + idx] = tf32r(e[q] - hi);
        }
    }
    __syncthreads();

    // Load this warp's A fragments into registers ONCE (64 regs).
    uint4 ahr[8], alr[8];
#pragma unroll
    for (int kk = 0; kk < 8; kk++) {
        ahr[kk] = *(const uint4*)(smem + A_HI_OFF + w * 1024 + kk * 128 + lane * 4);
        alr[kk] = *(const uint4*)(smem + A_LO_OFF + w * 1024 + kk * 128 + lane * 4);
    }

    unsigned long long best0 = ~0ull, best1 = ~0ull;   // rows g, g+8
    float acc[8][4];

    for (int p = 0; p < 32; p++) {
        CP_WAIT0();
        __syncthreads();

        if (p + 1 < 32) {
            const int pc = (p + 1) >> 1;
            const float* src = (((p + 1) & 1) ? g_Blo : g_Bhi) + pc * CHUNK_F;
            const uint32_t dstb =
                sbase + (uint32_t)((((p + 1) & 1) ? B1_OFF : B0_OFF)) * 4u;
#pragma unroll
            for (int q = 0; q < 5; q++)
                CP_ASYNC16(dstb + (uint32_t)(tid * L_STRIDE + q * 4) * 4u,
                           src + tid * L_STRIDE + q * 4);
            CP_COMMIT();
        }

        const float* B = smem + ((p & 1) ? B1_OFF : B0_OFF);

        if (!(p & 1)) {   // hi chunk: Xhi*Bhi + Xlo*Bhi, reset acc
#pragma unroll
            for (int nt = 0; nt < 8; nt++)
#pragma unroll
                for (int c = 0; c < 4; c++) acc[nt][c] = 0.f;
#pragma unroll
            for (int kk2 = 0; kk2 < 4; kk2++) {
#pragma unroll
                for (int nt = 0; nt < 8; nt++) {
                    uint4 bb = *(const uint4*)(B + nt * NT_STRIDE + lane * L_STRIDE + kk2 * 4);
                    MMA_TF32(acc[nt], ahr[2 * kk2 + 0], bb.x, bb.y);
                    MMA_TF32(acc[nt], ahr[2 * kk2 + 1], bb.z, bb.w);
                    MMA_TF32(acc[nt], alr[2 * kk2 + 0], bb.x, bb.y);
                    MMA_TF32(acc[nt], alr[2 * kk2 + 1], bb.z, bb.w);
                }
            }
        } else {          // lo chunk: Xhi*Blo, then epilogue
#pragma unroll
            for (int kk2 = 0; kk2 < 4; kk2++) {
#pragma unroll
                for (int nt = 0; nt < 8; nt++) {
                    uint4 bb = *(const uint4*)(B + nt * NT_STRIDE + lane * L_STRIDE + kk2 * 4);
                    MMA_TF32(acc[nt], ahr[2 * kk2 + 0], bb.x, bb.y);
                    MMA_TF32(acc[nt], ahr[2 * kk2 + 1], bb.z, bb.w);
                }
            }
            // d2 = ||c||^2 - 2 S. D frag rows g (c0,c1), g+8 (c2,c3).
            const int chunk = p >> 1;
#pragma unroll
            for (int nt = 0; nt < 8; nt++) {
                const int cols0 = chunk * 64 + nt * 8 + 2 * tig;
                float2 nrm = __ldg((const float2*)(g_cnorm + cols0));
                float d2;
                unsigned long long key;
                d2 = fmaf(-2.f, acc[nt][0], nrm.x);
                key = ((unsigned long long)ord_f32(d2) << 32) | (unsigned)cols0;
                if (key < best0) best0 = key;
                d2 = fmaf(-2.f, acc[nt][1], nrm.y);
                key = ((unsigned long long)ord_f32(d2) << 32) | (unsigned)(cols0 + 1);
                if (key < best0) best0 = key;
                d2 = fmaf(-2.f, acc[nt][2], nrm.x);
                key = ((unsigned long long)ord_f32(d2) << 32) | (unsigned)cols0;
                if (key < best1) best1 = key;
                d2 = fmaf(-2.f, acc[nt][3], nrm.y);
                key = ((unsigned long long)ord_f32(d2) << 32) | (unsigned)(cols0 + 1);
                if (key < best1) best1 = key;
            }
        }
    }

    // Reduce across the 4 lanes of each group.
#pragma unroll
    for (int off = 1; off <= 2; off <<= 1) {
        unsigned long long t;
        t = __shfl_xor_sync(0xFFFFFFFFu, best0, off); if (t < best0) best0 = t;
        t = __shfl_xor_sync(0xFFFFFFFFu, best1, off); if (t < best1) best1 = t;
    }

    __syncthreads();
    int* bidx = (int*)smem;   // 128 ints
    if (tig == 0) {
        bidx[w * 16 + g]     = (int)(best0 & 0xFFFFFFFFull);
        bidx[w * 16 + g + 8] = (int)(best1 & 0xFFFFFFFFull);
    }
    __syncthreads();

    // Gather winning rows coalesced, then transposed store.
    float* tmp = smem + 256;   // [128][68]
    for (int i = tid; i < PTS * 16; i += NTHREADS) {
        int pp = i >> 4;
        int d4 = (i & 15) * 4;
        *(float4*)(tmp + pp * 68 + d4) =
            *(const float4*)(cb + (size_t)bidx[pp] * DD + d4);
    }
    __syncthreads();
    float* qbase = out + (size_t)b * (DD * 4096) + (size_t)h0 * 64;
    for (int i = tid; i < DD * 32; i += NTHREADS) {
        int d  = i >> 5;
        int p4 = (i & 31) * 4;
        float4 v;
        v.x = tmp[(p4 + 0) * 68 + d];
        v.y = tmp[(p4 + 1) * 68 + d];
        v.z = tmp[(p4 + 2) * 68 + d];
        v.w = tmp[(p4 + 3) * 68 + d];
        *(float4*)(qbase + (size_t)d * 4096 + (p4 >> 6) * 64 + (p4 & 63)) = v;
    }

    if (write_idx && tid < PTS) {
        out[(size_t)4194304 + (size_t)bh0 * 64 + tid] = (float)bidx[tid];
    }
}

// ---------------- launch -----------------------------------------------------
extern "C" void kernel_launch(void* const* d_in, const int* in_sizes, int n_in,
                              void* d_out, int out_size) {
    const float* x  = (const float*)d_in[0];
    const float* cb = (const float*)d_in[1];
    if (n_in >= 2 && in_sizes[0] == KTOT * DD && in_sizes[1] == 16 * 64 * 64 * 64) {
        x  = (const float*)d_in[1];
        cb = (const float*)d_in[0];
    }
    float* out = (float*)d_out;

    const int smem_bytes = SMEM_FLOATS * (int)sizeof(float);
    cudaFuncSetAttribute(vq_main, cudaFuncAttributeMaxDynamicSharedMemorySize,
                         smem_bytes);

    int write_idx = (out_size >= 4194304 + 65536) ? 1 : 0;
    prep_cb<<<(KTOT + 255) / 256, 256>>>(cb);
    vq_main<<<512, NTHREADS, smem_bytes>>>(x, cb, out, write_idx);
}